// round 1
// baseline (speedup 1.0000x reference)
#include <cuda_runtime.h>

#define CC   10
#define NBIN 49
#define HH   34
#define WW   34
#define HW   (HH * WW)          // 1156
#define SLICE (HW * CC)         // 11560 floats = 46240 B
#define KDIM (CC * NBIN)        // 490
#define NMAX 30000

// Scratch (static device allocations are allowed)
__device__ float g_ft_t[NBIN * SLICE];     // [bin][y*34+x][c]
__device__ float g_out_t[KDIM * NMAX];     // [k = c*49+bin][n]

// ---------------------------------------------------------------------------
// Kernel A: ft (1, C*49, 34, 34) -> ft_t [bin][pos][c]
// ---------------------------------------------------------------------------
__global__ void k_transpose_ft(const float* __restrict__ ft) {
    int idx = blockIdx.x * blockDim.x + threadIdx.x;
    if (idx >= NBIN * SLICE) return;
    int c    = idx % CC;
    int rest = idx / CC;
    int pos  = rest % HW;
    int bin  = rest / HW;
    g_ft_t[idx] = ft[(c * NBIN + bin) * HW + pos];
}

// ---------------------------------------------------------------------------
// Kernel B: per (roi, bin) build 3x3 weight stencil, apply to 10 channels
// ---------------------------------------------------------------------------
__global__ __launch_bounds__(256) void k_roi(const float* __restrict__ rois, int N) {
    __shared__ float sm[SLICE];
    const int bin = blockIdx.y;

    // Stage this bin's 34x34x10 slice into shared memory (vectorized).
    {
        const float4* src = reinterpret_cast<const float4*>(g_ft_t + bin * SLICE);
        float4*       dst = reinterpret_cast<float4*>(sm);
        for (int i = threadIdx.x; i < SLICE / 4; i += 256) dst[i] = src[i];
    }
    __syncthreads();

    const int n = blockIdx.x * 256 + threadIdx.x;
    if (n >= N) return;

    const int ph = bin / 7, pw = bin % 7;

    float rsw = __ldg(rois + n * 5 + 1) * 0.125f;
    float rsh = __ldg(rois + n * 5 + 2) * 0.125f;
    float rew = __ldg(rois + n * 5 + 3) * 0.125f;
    float reh = __ldg(rois + n * 5 + 4) * 0.125f;
    float rh = reh - rsh; rh = (rh > 0.1f) ? rh : 0.1f;
    float rw = rew - rsw; rw = (rw > 0.1f) ? rw : 0.1f;
    float bsh = rh / 7.0f, bsw = rw / 7.0f;
    float sub_h = bsh * 0.25f, sub_w = bsw * 0.25f;
    float hstart = floorf(rsh + (float)ph * bsh);
    float wstart = floorf(rsw + (float)pw * bsw);

    // 3x3 window anchor (all taps of all 16 samples land in [X0,X0+2]x[Y0,Y0+2]
    // after clipping, because 3*sub < 1).
    const int X0 = (int)fminf(fmaxf(wstart, 0.f), (float)(WW - 3));
    const int Y0 = (int)fminf(fmaxf(hstart, 0.f), (float)(HH - 3));

    float W9[9];
#pragma unroll
    for (int i = 0; i < 9; i++) W9[i] = 0.f;
    float cnt = 0.f;

#pragma unroll
    for (int ih = 0; ih < 4; ih++) {
        float h = hstart + ((float)ih + 0.5f) * sub_h;
        bool hok = (h > -1.f) && (h < (float)HH);
        float y1f = floorf(h), y2f = ceilf(h);
        bool y1v = (y1f >= 0.f) && (y1f < (float)HH);
        bool y2v = (y2f >= 0.f) && (y2f < (float)HH);
        bool yv  = y1v || y2v;
        float y1c = fminf(fmaxf(y1f, 0.f), 33.f);
        float y2c = fminf(fmaxf(y2f, 0.f), 33.f);
        float dy = h - y1c;                 // uses CLIPPED y1 (matches reference)
        int ry1 = (int)y1c - Y0;
        int ry2 = (int)y2c - Y0;
        float ay = 1.f - dy, by = dy;
        float wy0 = ((ry1 == 0) ? ay : 0.f) + ((ry2 == 0) ? by : 0.f);
        float wy1 = ((ry1 == 1) ? ay : 0.f) + ((ry2 == 1) ? by : 0.f);
        float wy2 = ((ry1 == 2) ? ay : 0.f) + ((ry2 == 2) ? by : 0.f);

#pragma unroll
        for (int iw = 0; iw < 4; iw++) {
            float w = wstart + ((float)iw + 0.5f) * sub_w;
            bool keep = hok && (w > -1.f) && (w < (float)WW);
            float x1f = floorf(w), x2f = ceilf(w);
            bool x1v = (x1f >= 0.f) && (x1f < (float)WW);
            bool x2v = (x2f >= 0.f) && (x2f < (float)WW);
            float x1c = fminf(fmaxf(x1f, 0.f), 33.f);
            float x2c = fminf(fmaxf(x2f, 0.f), 33.f);
            float dx = w - x1c;             // uses CLIPPED x1 (matches reference)
            int cx1 = (int)x1c - X0;
            int cx2 = (int)x2c - X0;
            float kf = keep ? 1.f : 0.f;
            cnt += kf;
            float ax = kf * (1.f - dx);
            float bx = kf * dx;
            float wx0 = ((cx1 == 0) ? ax : 0.f) + ((cx2 == 0) ? bx : 0.f);
            float wx1 = ((cx1 == 1) ? ax : 0.f) + ((cx2 == 1) ? bx : 0.f);
            float wx2 = ((cx1 == 2) ? ax : 0.f) + ((cx2 == 2) ? bx : 0.f);
            // rank-1 outer-product accumulation into 3x3 stencil
            W9[0] = fmaf(wy0, wx0, W9[0]); W9[1] = fmaf(wy0, wx1, W9[1]); W9[2] = fmaf(wy0, wx2, W9[2]);
            W9[3] = fmaf(wy1, wx0, W9[3]); W9[4] = fmaf(wy1, wx1, W9[4]); W9[5] = fmaf(wy1, wx2, W9[5]);
            W9[6] = fmaf(wy2, wx0, W9[6]); W9[7] = fmaf(wy2, wx1, W9[7]); W9[8] = fmaf(wy2, wx2, W9[8]);
            // bad11: reference zeroes ONLY v11 in this case -> subtract its weight.
            bool bad11 = ((!x1v) || (!x2v)) && yv;
            if (keep && bad11) {            // rare (image-edge rois only)
                float corr = (1.f - dx) * (1.f - dy);
                int id = ry1 * 3 + cx1;
                if      (id == 0) W9[0] -= corr;
                else if (id == 1) W9[1] -= corr;
                else if (id == 2) W9[2] -= corr;
                else if (id == 3) W9[3] -= corr;
                else if (id == 4) W9[4] -= corr;
                else if (id == 5) W9[5] -= corr;
                else if (id == 6) W9[6] -= corr;
                else if (id == 7) W9[7] -= corr;
                else              W9[8] -= corr;
            }
        }
    }

    if (cnt > 0.f) {
        float inv = 1.f / cnt;
#pragma unroll
        for (int i = 0; i < 9; i++) W9[i] *= inv;
    }

    // Apply stencil: 9 texels x 10 channels from shared memory.
    float a[CC];
#pragma unroll
    for (int i = 0; i < CC; i++) a[i] = 0.f;
    const float* base = sm + (Y0 * WW + X0) * CC;
#pragma unroll
    for (int r = 0; r < 3; r++) {
#pragma unroll
        for (int c2 = 0; c2 < 3; c2++) {
            float wgt = W9[r * 3 + c2];
            if (wgt != 0.f) {               // col/row 2 usually unused -> skip
                const float* t = base + (r * WW + c2) * CC;   // 8B-aligned
                float2 v0 = *reinterpret_cast<const float2*>(t + 0);
                float2 v1 = *reinterpret_cast<const float2*>(t + 2);
                float2 v2 = *reinterpret_cast<const float2*>(t + 4);
                float2 v3 = *reinterpret_cast<const float2*>(t + 6);
                float2 v4 = *reinterpret_cast<const float2*>(t + 8);
                a[0] = fmaf(wgt, v0.x, a[0]); a[1] = fmaf(wgt, v0.y, a[1]);
                a[2] = fmaf(wgt, v1.x, a[2]); a[3] = fmaf(wgt, v1.y, a[3]);
                a[4] = fmaf(wgt, v2.x, a[4]); a[5] = fmaf(wgt, v2.y, a[5]);
                a[6] = fmaf(wgt, v3.x, a[6]); a[7] = fmaf(wgt, v3.y, a[7]);
                a[8] = fmaf(wgt, v4.x, a[8]); a[9] = fmaf(wgt, v4.y, a[9]);
            }
        }
    }

    // Coalesced store to scratch [c*49+bin][n]
#pragma unroll
    for (int c2 = 0; c2 < CC; c2++)
        g_out_t[(c2 * NBIN + bin) * N + n] = a[c2];
}

// ---------------------------------------------------------------------------
// Kernel C: tiled transpose scratch[k][n] -> out[n][k]   (k = c*49+bin)
// ---------------------------------------------------------------------------
__global__ void k_transpose_out(float* __restrict__ out, int N) {
    __shared__ float tile[32][33];
    int n0 = blockIdx.x * 32;
    int k0 = blockIdx.y * 32;
    int tx = threadIdx.x, ty = threadIdx.y;
#pragma unroll
    for (int i = 0; i < 32; i += 8) {
        int k = k0 + ty + i, n = n0 + tx;
        if (k < KDIM && n < N) tile[ty + i][tx] = g_out_t[k * N + n];
    }
    __syncthreads();
#pragma unroll
    for (int i = 0; i < 32; i += 8) {
        int n = n0 + ty + i, k = k0 + tx;
        if (n < N && k < KDIM) out[n * KDIM + k] = tile[tx][ty + i];
    }
}

// ---------------------------------------------------------------------------
extern "C" void kernel_launch(void* const* d_in, const int* in_sizes, int n_in,
                              void* d_out, int out_size) {
    const float* ft   = (const float*)d_in[0];
    const float* rois = (const float*)d_in[1];
    float*       out  = (float*)d_out;
    int N = in_sizes[1] / 5;
    if (N > NMAX) N = NMAX;

    k_transpose_ft<<<(NBIN * SLICE + 255) / 256, 256>>>(ft);

    dim3 gb((N + 255) / 256, NBIN);
    k_roi<<<gb, 256>>>(rois, N);

    dim3 gc((N + 31) / 32, (KDIM + 31) / 32);
    k_transpose_out<<<gc, dim3(32, 8)>>>(out, N);
}

// round 2
// speedup vs baseline: 1.3883x; 1.3883x over previous
#include <cuda_runtime.h>

#define CC   10
#define NBIN 49
#define HH   34
#define WW   34
#define HW   (HH * WW)          // 1156
#define SLICE (HW * CC)         // 11560 floats = 46240 B
#define KDIM (CC * NBIN)        // 490
#define NMAX 30000
#define BLK  512

// Scratch (static device allocations are allowed)
__device__ float g_ft_t[NBIN * SLICE];     // [bin][y*34+x][c]
__device__ float g_out_t[KDIM * NMAX];     // [k = c*49+bin][n]

// ---------------------------------------------------------------------------
// Kernel A: ft (1, C*49, 34, 34) -> ft_t [bin][pos][c]
// ---------------------------------------------------------------------------
__global__ void k_transpose_ft(const float* __restrict__ ft) {
    int idx = blockIdx.x * blockDim.x + threadIdx.x;
    if (idx >= NBIN * SLICE) return;
    int c    = idx % CC;
    int rest = idx / CC;
    int pos  = rest % HW;
    int bin  = rest / HW;
    g_ft_t[idx] = ft[(c * NBIN + bin) * HW + pos];
}

// ---------------------------------------------------------------------------
// Kernel B: per (roi, bin). Separable stencil:
//   W9 = WY (x) WX  -  CY (x) CX,   cnt = cntY * cntX
// then apply 3x3 stencil to 10 channels from the bin's smem slice.
// ---------------------------------------------------------------------------
__global__ __launch_bounds__(BLK) void k_roi(const float* __restrict__ rois, int N) {
    __shared__ float sm[SLICE];
    const int bin = blockIdx.y;

    // Stage this bin's 34x34x10 slice into shared memory (float4, conflict-free).
    {
        const float4* src = reinterpret_cast<const float4*>(g_ft_t + bin * SLICE);
        float4*       dst = reinterpret_cast<float4*>(sm);
        for (int i = threadIdx.x; i < SLICE / 4; i += BLK) dst[i] = src[i];
    }
    __syncthreads();

    const int n = blockIdx.x * BLK + threadIdx.x;
    if (n >= N) return;

    const int ph = bin / 7, pw = bin % 7;

    float rsw = __ldg(rois + n * 5 + 1) * 0.125f;
    float rsh = __ldg(rois + n * 5 + 2) * 0.125f;
    float rew = __ldg(rois + n * 5 + 3) * 0.125f;
    float reh = __ldg(rois + n * 5 + 4) * 0.125f;
    float rh = reh - rsh; rh = (rh > 0.1f) ? rh : 0.1f;
    float rw = rew - rsw; rw = (rw > 0.1f) ? rw : 0.1f;
    float bsh = rh / 7.0f, bsw = rw / 7.0f;
    float sub_h = bsh * 0.25f, sub_w = bsw * 0.25f;
    float hstart = floorf(rsh + (float)ph * bsh);
    float wstart = floorf(rsw + (float)pw * bsw);

    // 3x3 window anchor. All taps (clipped) land in [X0..X0+2]x[Y0..Y0+2]
    // because the 4 samples span < 1.125 px and hstart/wstart are integers.
    const int X0 = (int)fminf(fmaxf(wstart, 0.f), (float)(WW - 3));
    const int Y0 = (int)fminf(fmaxf(hstart, 0.f), (float)(HH - 3));

    // ---- Y pass (4 iters) ----
    float WY0 = 0.f, WY1 = 0.f, WY2 = 0.f;
    float CY0 = 0.f, CY1 = 0.f, CY2 = 0.f;
    float cntY = 0.f;
#pragma unroll
    for (int ih = 0; ih < 4; ih++) {
        float h = hstart + ((float)ih + 0.5f) * sub_h;
        bool hok = (h > -1.f) && (h < (float)HH);
        float y1f = floorf(h), y2f = ceilf(h);
        bool yv = ((y1f >= 0.f) && (y1f < (float)HH)) ||
                  ((y2f >= 0.f) && (y2f < (float)HH));
        float y1c = fminf(fmaxf(y1f, 0.f), 33.f);
        float y2c = fminf(fmaxf(y2f, 0.f), 33.f);
        float dy = h - y1c;                  // clipped y1 (matches reference)
        int ry1 = (int)y1c - Y0;
        int ry2 = (int)y2c - Y0;
        float hokf = hok ? 1.f : 0.f;
        cntY += hokf;
        float ay = hokf * (1.f - dy), by = hokf * dy;
        WY0 += ((ry1 == 0) ? ay : 0.f) + ((ry2 == 0) ? by : 0.f);
        WY1 += ((ry1 == 1) ? ay : 0.f) + ((ry2 == 1) ? by : 0.f);
        WY2 += ((ry1 == 2) ? ay : 0.f) + ((ry2 == 2) ? by : 0.f);
        float cy = (hok && yv) ? (1.f - dy) : 0.f;
        CY0 += (ry1 == 0) ? cy : 0.f;
        CY1 += (ry1 == 1) ? cy : 0.f;
        CY2 += (ry1 == 2) ? cy : 0.f;
    }

    // ---- X pass (4 iters) ----
    float WX0 = 0.f, WX1 = 0.f, WX2 = 0.f;
    float CX0 = 0.f, CX1 = 0.f, CX2 = 0.f;
    float cntX = 0.f;
#pragma unroll
    for (int iw = 0; iw < 4; iw++) {
        float w = wstart + ((float)iw + 0.5f) * sub_w;
        bool wok = (w > -1.f) && (w < (float)WW);
        float x1f = floorf(w), x2f = ceilf(w);
        bool badx = !((x1f >= 0.f) && (x1f < (float)WW)) ||
                    !((x2f >= 0.f) && (x2f < (float)WW));
        float x1c = fminf(fmaxf(x1f, 0.f), 33.f);
        float x2c = fminf(fmaxf(x2f, 0.f), 33.f);
        float dx = w - x1c;                  // clipped x1 (matches reference)
        int cx1 = (int)x1c - X0;
        int cx2 = (int)x2c - X0;
        float wokf = wok ? 1.f : 0.f;
        cntX += wokf;
        float ax = wokf * (1.f - dx), bx = wokf * dx;
        WX0 += ((cx1 == 0) ? ax : 0.f) + ((cx2 == 0) ? bx : 0.f);
        WX1 += ((cx1 == 1) ? ax : 0.f) + ((cx2 == 1) ? bx : 0.f);
        WX2 += ((cx1 == 2) ? ax : 0.f) + ((cx2 == 2) ? bx : 0.f);
        float cx = (wok && badx) ? (1.f - dx) : 0.f;
        CX0 += (cx1 == 0) ? cx : 0.f;
        CX1 += (cx1 == 1) ? cx : 0.f;
        CX2 += (cx1 == 2) ? cx : 0.f;
    }

    // ---- combine: W9 = WY (x) WX - CY (x) CX ; normalize by cnt ----
    float cnt = cntY * cntX;
    float inv = (cnt > 0.f) ? (1.f / cnt) : 1.f;
    float wy0 = WY0 * inv, wy1 = WY1 * inv, wy2 = WY2 * inv;
    float W9[9];
    W9[0] = fmaf(wy0, WX0, -CY0 * CX0 * inv);
    W9[1] = fmaf(wy0, WX1, -CY0 * CX1 * inv);
    W9[2] = fmaf(wy0, WX2, -CY0 * CX2 * inv);
    W9[3] = fmaf(wy1, WX0, -CY1 * CX0 * inv);
    W9[4] = fmaf(wy1, WX1, -CY1 * CX1 * inv);
    W9[5] = fmaf(wy1, WX2, -CY1 * CX2 * inv);
    W9[6] = fmaf(wy2, WX0, -CY2 * CX0 * inv);
    W9[7] = fmaf(wy2, WX1, -CY2 * CX1 * inv);
    W9[8] = fmaf(wy2, WX2, -CY2 * CX2 * inv);

    // ---- apply stencil: up to 9 texels x 10 channels from shared memory ----
    float a[CC];
#pragma unroll
    for (int i = 0; i < CC; i++) a[i] = 0.f;
    const float* base = sm + (Y0 * WW + X0) * CC;
#pragma unroll
    for (int r = 0; r < 3; r++) {
#pragma unroll
        for (int c2 = 0; c2 < 3; c2++) {
            float wgt = W9[r * 3 + c2];
            if (wgt != 0.f) {                // cols/rows past the span skip
                const float* t = base + (r * WW + c2) * CC;   // 8B-aligned
                float2 v0 = *reinterpret_cast<const float2*>(t + 0);
                float2 v1 = *reinterpret_cast<const float2*>(t + 2);
                float2 v2 = *reinterpret_cast<const float2*>(t + 4);
                float2 v3 = *reinterpret_cast<const float2*>(t + 6);
                float2 v4 = *reinterpret_cast<const float2*>(t + 8);
                a[0] = fmaf(wgt, v0.x, a[0]); a[1] = fmaf(wgt, v0.y, a[1]);
                a[2] = fmaf(wgt, v1.x, a[2]); a[3] = fmaf(wgt, v1.y, a[3]);
                a[4] = fmaf(wgt, v2.x, a[4]); a[5] = fmaf(wgt, v2.y, a[5]);
                a[6] = fmaf(wgt, v3.x, a[6]); a[7] = fmaf(wgt, v3.y, a[7]);
                a[8] = fmaf(wgt, v4.x, a[8]); a[9] = fmaf(wgt, v4.y, a[9]);
            }
        }
    }

    // Coalesced store to scratch [c*49+bin][n]
#pragma unroll
    for (int c2 = 0; c2 < CC; c2++)
        g_out_t[(c2 * NBIN + bin) * N + n] = a[c2];
}

// ---------------------------------------------------------------------------
// Kernel C: tiled transpose scratch[k][n] -> out[n][k]   (k = c*49+bin)
// ---------------------------------------------------------------------------
__global__ void k_transpose_out(float* __restrict__ out, int N) {
    __shared__ float tile[32][33];
    int n0 = blockIdx.x * 32;
    int k0 = blockIdx.y * 32;
    int tx = threadIdx.x, ty = threadIdx.y;
#pragma unroll
    for (int i = 0; i < 32; i += 8) {
        int k = k0 + ty + i, n = n0 + tx;
        if (k < KDIM && n < N) tile[ty + i][tx] = g_out_t[k * N + n];
    }
    __syncthreads();
#pragma unroll
    for (int i = 0; i < 32; i += 8) {
        int n = n0 + ty + i, k = k0 + tx;
        if (n < N && k < KDIM) out[n * KDIM + k] = tile[tx][ty + i];
    }
}

// ---------------------------------------------------------------------------
extern "C" void kernel_launch(void* const* d_in, const int* in_sizes, int n_in,
                              void* d_out, int out_size) {
    const float* ft   = (const float*)d_in[0];
    const float* rois = (const float*)d_in[1];
    float*       out  = (float*)d_out;
    int N = in_sizes[1] / 5;
    if (N > NMAX) N = NMAX;

    k_transpose_ft<<<(NBIN * SLICE + 255) / 256, 256>>>(ft);

    dim3 gb((N + BLK - 1) / BLK, NBIN);
    k_roi<<<gb, BLK>>>(rois, N);

    dim3 gc((N + 31) / 32, (KDIM + 31) / 32);
    k_transpose_out<<<gc, dim3(32, 8)>>>(out, N);
}